// round 11
// baseline (speedup 1.0000x reference)
#include <cuda_runtime.h>

typedef unsigned long long ull;

#define TT   512
#define BB   256
#define DIN  85
#define HH   512
#define NOUT 33

constexpr size_t GSc = (size_t)TT * HH * BB;   // elements per gate

// Scratch (allocation-free rule: __device__ globals)
__device__ float g_pre[4 * GSc];   // [gate][t][h][b]
__device__ float g_hid[GSc];       // [t][h][b]
__device__ unsigned g_bar2[2];     // monotonic barrier counters (parity of t)

// ---------- packed fp32x2 helpers ----------
__device__ __forceinline__ ull pack2(float x, float y) {
    ull v;
    asm("mov.b64 %0, {%1, %2};" : "=l"(v)
        : "r"(__float_as_uint(x)), "r"(__float_as_uint(y)));
    return v;
}
__device__ __forceinline__ float2 unpack2(ull v) {
    unsigned a, b;
    asm("mov.b64 {%0, %1}, %2;" : "=r"(a), "=r"(b) : "l"(v));
    return make_float2(__uint_as_float(a), __uint_as_float(b));
}
#define FMA2(acc, a, b) \
    asm("fma.rn.f32x2 %0, %1, %2, %0;" : "+l"(acc) : "l"(a), "l"(b))

// ---------- fast activations (validated rel err ~4e-7 final) ----------
__device__ __forceinline__ float sigf(float x) {
    x = fminf(fmaxf(x, -30.f), 30.f);
    return __fdividef(1.f, 1.f + __expf(-x));
}
__device__ __forceinline__ float tanh_fast(float x) {
    x = fminf(fmaxf(x, -15.f), 15.f);
    float e = __expf(-2.f * x);
    return __fdividef(1.f - e, 1.f + e);
}

// ---------- cp.async helpers ----------
__device__ __forceinline__ unsigned smem_u32(const void* p) {
    return (unsigned)__cvta_generic_to_shared(p);
}
__device__ __forceinline__ void cp16(unsigned dst, const void* src) {
    asm volatile("cp.async.cg.shared.global [%0], [%1], 16;" :: "r"(dst), "l"(src));
}
#define CP_COMMIT() asm volatile("cp.async.commit_group;")
template<int N> __device__ __forceinline__ void cp_wait() {
    asm volatile("cp.async.wait_group %0;" :: "n"(N));
}

// =====================================================================
// Phase 1: input projections  pre[g][t][h][b] = sum_i x[t,b,i] * Wxg[h,i]
// One CTA per t; warp processes 4 gate-rows at a time (x loads amortized).
// =====================================================================
__global__ void __launch_bounds__(256, 1) k_input_proj(
    const float* __restrict__ x,
    const float* __restrict__ Wxi, const float* __restrict__ Wxf,
    const float* __restrict__ Wxo, const float* __restrict__ Wxc)
{
    extern __shared__ float xs[];          // [85][258]
    const int t = blockIdx.x;
    const float* xt = x + (size_t)t * BB * DIN;
    for (int idx = threadIdx.x; idx < BB * DIN; idx += 256) {
        int b = idx / DIN;
        int i = idx - b * DIN;
        xs[i * 258 + b] = xt[idx];
    }
    __syncthreads();

    const int warp = threadIdx.x >> 5;
    const int lane = threadIdx.x & 31;

    for (int r4 = warp * 4; r4 < 4 * HH; r4 += 32) {
        const int g = r4 >> 9;
        const int h = r4 & (HH - 1);
        const float* wrow;
        if      (g == 0) wrow = Wxi + h * DIN;
        else if (g == 1) wrow = Wxf + h * DIN;
        else if (g == 2) wrow = Wxo + h * DIN;
        else             wrow = Wxc + h * DIN;

        ull acc[4][4];
#pragma unroll
        for (int rr = 0; rr < 4; rr++)
#pragma unroll
            for (int q = 0; q < 4; q++) acc[rr][q] = 0;

#pragma unroll 5
        for (int i = 0; i < DIN; i++) {
            const ull* xr = (const ull*)(xs + i * 258);
            ull x0 = xr[lane], x1 = xr[lane + 32];
            ull x2 = xr[lane + 64], x3 = xr[lane + 96];
#pragma unroll
            for (int rr = 0; rr < 4; rr++) {
                float w = __ldg(wrow + rr * DIN + i);
                ull w2 = pack2(w, w);
                FMA2(acc[rr][0], w2, x0);
                FMA2(acc[rr][1], w2, x1);
                FMA2(acc[rr][2], w2, x2);
                FMA2(acc[rr][3], w2, x3);
            }
        }
#pragma unroll
        for (int rr = 0; rr < 4; rr++) {
            ull* pp = (ull*)(g_pre + (size_t)g * GSc +
                             ((size_t)t * HH + h + rr) * BB);
            pp[lane]      = acc[rr][0];
            pp[lane + 32] = acc[rr][1];
            pp[lane + 64] = acc[rr][2];
            pp[lane + 96] = acc[rr][3];
        }
    }
}

// =====================================================================
// Phase 2: persistent recurrence. 128 CTAs x 256 threads, grid barrier.
// CTA tile: 8 h (32 gate rows) x 128 b.
//   grp  = blockIdx.x & 1   -> b0 = grp*128
//   hblk = blockIdx.x >> 1  -> h0 = hblk*8
// Thread: hm = tid & 7 (one h, 4 gates), bq = tid >> 3 (4 b values).
// SMEM: sW[512 k][8 h][{wI,wI},{wF,wF},{wO,wO},{wC,wC}] (128 KB, dup'd
//       so h float4 loads are natural b-pairs -> zero pack MOVs)
//       sH quad buffer 4 x [32 k][128 b] (64 KB) via cp.async depth-2.
// Barrier: REDG arrival + monotonic target poll (no reset, no contention).
// =====================================================================
__global__ void __launch_bounds__(256, 1) k_lstm_rec(
    const float* __restrict__ Whi, const float* __restrict__ Whf,
    const float* __restrict__ Who, const float* __restrict__ Whc,
    const float* __restrict__ bhi, const float* __restrict__ bhf,
    const float* __restrict__ bho, const float* __restrict__ bhc)
{
    extern __shared__ float smem_f[];
    ull*   sW = (ull*)smem_f;               // 16384 ull  = 128 KB
    float* sH = smem_f + 32768;             // 4 x 4096 f = 64 KB
    const unsigned sH_u32 = smem_u32(sH);

    const int tid  = threadIdx.x;
    const int hm   = tid & 7;
    const int bq   = tid >> 3;              // 0..31
    const int grp  = blockIdx.x & 1;
    const int hblk = blockIdx.x >> 1;       // 0..63
    const int h0   = hblk * 8;
    const int h    = h0 + hm;
    const int b0   = grp * 128;
    const int bb   = b0 + bq * 4;           // this thread's 4 b values

    // One-time duplicated W: sW[k*32 + hl*4 + g] = {w,w} of gate g, row h0+hl
    for (int idx = tid; idx < 512 * 32; idx += 256) {
        int k  = idx >> 5;
        int r  = idx & 31;
        int hl = r >> 2;
        int g  = r & 3;
        int src = (h0 + hl) * HH + k;
        float w;
        if      (g == 0) w = Whi[src];
        else if (g == 1) w = Whf[src];
        else if (g == 2) w = Who[src];
        else             w = Whc[src];
        sW[idx] = pack2(w, w);
    }
    const float bi  = bhi[h], bf_ = bhf[h], bo = bho[h], bc = bhc[h];
    float C0 = 0.f, C1 = 0.f, C2 = 0.f, C3 = 0.f;
    __syncthreads();

    // per-thread W pointer: per k, two ulonglong2 at k*16 + hm*2 (+1)
    const ulonglong2* wpt = (const ulonglong2*)sW + hm * 2;

#pragma unroll 1
    for (int t = 0; t < TT; t++) {
        // Prefetch gate pre-activations (hidden under the GEMM)
        const float* pb = g_pre + ((size_t)t * HH + h) * BB + bb;
        float4 xi = *(const float4*)(pb);
        float4 xf = *(const float4*)(pb + GSc);
        float4 xo = *(const float4*)(pb + 2 * GSc);
        float4 xc = *(const float4*)(pb + 3 * GSc);

        ull aI0 = 0, aI1 = 0, aF0 = 0, aF1 = 0;
        ull aO0 = 0, aO1 = 0, aC0 = 0, aC1 = 0;

        if (t > 0) {
            const float* hsrc = g_hid + (size_t)(t - 1) * HH * BB + b0;

            // stage chunks 0 and 1 (depth-2 pipeline)
#pragma unroll
            for (int n = 0; n < 2; n++) {
                const float* src = hsrc + (size_t)n * 32 * BB;
                unsigned dstb = sH_u32 + (unsigned)(n & 3) * 16384;
#pragma unroll
                for (int j = 0; j < 4; j++) {
                    int i = tid + j * 256;          // 0..1023
                    int row = i >> 5, col = i & 31;
                    cp16(dstb + (unsigned)i * 16, src + row * BB + col * 4);
                }
                CP_COMMIT();
            }

#pragma unroll 1
            for (int c = 0; c < 16; c++) {
                if (c < 14) {   // stage chunk c+2 into buf (c+2)&3
                    const float* src = hsrc + (size_t)(c + 2) * 32 * BB;
                    unsigned dstb = sH_u32 + (unsigned)((c + 2) & 3) * 16384;
#pragma unroll
                    for (int j = 0; j < 4; j++) {
                        int i = tid + j * 256;
                        int row = i >> 5, col = i & 31;
                        cp16(dstb + (unsigned)i * 16, src + row * BB + col * 4);
                    }
                    CP_COMMIT();
                    cp_wait<2>();
                } else if (c == 14) {
                    cp_wait<1>();
                } else {
                    cp_wait<0>();
                }
                __syncthreads();   // single sync per chunk (quad buffer safe)

                const ulonglong2* hpt =
                    (const ulonglong2*)(sH + (c & 3) * 4096) + bq;

#pragma unroll 4
                for (int kl = 0; kl < 32; kl++) {
                    const int k16 = (c * 32 + kl) * 16;
                    ulonglong2 wIF = wpt[k16];       // {wI,wI},{wF,wF}
                    ulonglong2 wOC = wpt[k16 + 1];   // {wO,wO},{wC,wC}
                    ulonglong2 hv  = hpt[kl * 32];   // {b0,b1},{b2,b3}
                    FMA2(aI0, wIF.x, hv.x); FMA2(aI1, wIF.x, hv.y);
                    FMA2(aF0, wIF.y, hv.x); FMA2(aF1, wIF.y, hv.y);
                    FMA2(aO0, wOC.x, hv.x); FMA2(aO1, wOC.x, hv.y);
                    FMA2(aC0, wOC.y, hv.x); FMA2(aC1, wOC.y, hv.y);
                }
            }
        }

        // ---- epilogue: gates -> cell update -> hidden state (4 b) ----
        float hv0, hv1, hv2, hv3;
        {
            float2 vI = unpack2(aI0), vF = unpack2(aF0);
            float2 vO = unpack2(aO0), vG = unpack2(aC0);
            float I = sigf(vI.x + xi.x + bi), F = sigf(vF.x + xf.x + bf_);
            float O = sigf(vO.x + xo.x + bo), G = tanh_fast(vG.x + xc.x + bc);
            C0 = F * C0 + I * G;  hv0 = O * tanh_fast(C0);
            I = sigf(vI.y + xi.y + bi);  F = sigf(vF.y + xf.y + bf_);
            O = sigf(vO.y + xo.y + bo);  G = tanh_fast(vG.y + xc.y + bc);
            C1 = F * C1 + I * G;  hv1 = O * tanh_fast(C1);
        }
        {
            float2 vI = unpack2(aI1), vF = unpack2(aF1);
            float2 vO = unpack2(aO1), vG = unpack2(aC1);
            float I = sigf(vI.x + xi.z + bi), F = sigf(vF.x + xf.z + bf_);
            float O = sigf(vO.x + xo.z + bo), G = tanh_fast(vG.x + xc.z + bc);
            C2 = F * C2 + I * G;  hv2 = O * tanh_fast(C2);
            I = sigf(vI.y + xi.w + bi);  F = sigf(vF.y + xf.w + bf_);
            O = sigf(vO.y + xo.w + bo);  G = tanh_fast(vG.y + xc.w + bc);
            C3 = F * C3 + I * G;  hv3 = O * tanh_fast(C3);
        }

        *(float4*)(g_hid + ((size_t)t * HH + h) * BB + bb) =
            make_float4(hv0, hv1, hv2, hv3);

        // ---- grid barrier: REDG arrival + monotonic target poll ----
        if (t < TT - 1) {
            __threadfence();
            __syncthreads();
            if (tid == 0) {
                unsigned p = (unsigned)t & 1u;
                atomicAdd(&g_bar2[p], 1u);          // return unused -> RED
                unsigned target = 128u * ((unsigned)(t >> 1) + 1u);
                while (*(volatile unsigned*)&g_bar2[p] < target) { }
                __threadfence();
            }
            __syncthreads();
        }
    }
}

// =====================================================================
// Phase 3: readout  out[t][b][o] = sum_h hid[t][h][b]*Wro[o][h] + bro[o]
// =====================================================================
__global__ void __launch_bounds__(256, 1) k_readout(
    const float* __restrict__ Wro, const float* __restrict__ bro,
    float* __restrict__ out)
{
    extern __shared__ float ws[];          // [33][512]
    for (int idx = threadIdx.x; idx < NOUT * HH; idx += 256)
        ws[idx] = Wro[idx];
    __syncthreads();

    const int warp = threadIdx.x >> 5;
    const int lane = threadIdx.x & 31;
    const int t = blockIdx.x;
    const int b = warp * 32 + lane;
    const float* hp = g_hid + (size_t)t * HH * BB + b;

    ull acc[NOUT];
#pragma unroll
    for (int o = 0; o < NOUT; o++) acc[o] = 0;

    for (int hh = 0; hh < HH; hh += 2) {
        float hv0 = hp[(size_t)hh * BB];
        float hv1 = hp[(size_t)(hh + 1) * BB];
        ull hv = pack2(hv0, hv1);
        const ull* wp = (const ull*)(ws + hh);
#pragma unroll
        for (int o = 0; o < NOUT; o++)
            FMA2(acc[o], hv, wp[o * 256]);
    }

    float* op = out + ((size_t)t * BB + b) * NOUT;
#pragma unroll
    for (int o = 0; o < NOUT; o++) {
        float2 v = unpack2(acc[o]);
        op[o] = v.x + v.y + bro[o];
    }
}

// =====================================================================
extern "C" void kernel_launch(void* const* d_in, const int* in_sizes, int n_in,
                              void* d_out, int out_size)
{
    const float* x   = (const float*)d_in[0];
    const float* Wxi = (const float*)d_in[1];
    const float* Wxf = (const float*)d_in[2];
    const float* Wxo = (const float*)d_in[3];
    const float* Wxc = (const float*)d_in[4];
    const float* Whi = (const float*)d_in[5];
    const float* bhi = (const float*)d_in[6];
    const float* Whf = (const float*)d_in[7];
    const float* bhf = (const float*)d_in[8];
    const float* Who = (const float*)d_in[9];
    const float* bho = (const float*)d_in[10];
    const float* Whc = (const float*)d_in[11];
    const float* bhc = (const float*)d_in[12];
    const float* Wro = (const float*)d_in[13];
    const float* bro = (const float*)d_in[14];
    float* out = (float*)d_out;

    // reset barrier counters (stream-ordered, graph-capturable)
    void* barptr = nullptr;
    cudaGetSymbolAddress(&barptr, g_bar2);
    cudaMemsetAsync(barptr, 0, sizeof(unsigned) * 2);

    const int smem_p1 = 85 * 258 * 4;               // 87,720 B
    const int smem_p2 = (32768 + 4 * 4096) * 4;     // 196,608 B
    const int smem_p3 = NOUT * HH * 4;              // 67,584 B

    cudaFuncSetAttribute(k_input_proj, cudaFuncAttributeMaxDynamicSharedMemorySize, smem_p1);
    cudaFuncSetAttribute(k_lstm_rec,   cudaFuncAttributeMaxDynamicSharedMemorySize, smem_p2);
    cudaFuncSetAttribute(k_readout,    cudaFuncAttributeMaxDynamicSharedMemorySize, smem_p3);

    k_input_proj<<<TT, 256, smem_p1>>>(x, Wxi, Wxf, Wxo, Wxc);
    k_lstm_rec<<<128, 256, smem_p2>>>(Whi, Whf, Who, Whc, bhi, bhf, bho, bhc);
    k_readout<<<TT, 256, smem_p3>>>(Wro, bro, out);
}

// round 12
// speedup vs baseline: 1.5540x; 1.5540x over previous
#include <cuda_runtime.h>

typedef unsigned long long ull;

#define TT   512
#define BB   256
#define DIN  85
#define HH   512
#define NOUT 33

constexpr size_t GSc = (size_t)TT * HH * BB;   // elements per gate

// Scratch (allocation-free rule: __device__ globals)
__device__ float g_pre[4 * GSc];   // [gate][t][h][b]
__device__ float g_hid[GSc];       // [t][h][b]
__device__ unsigned g_cnt = 0;
__device__ volatile unsigned g_gen = 0;

// ---------- packed fp32x2 helpers ----------
__device__ __forceinline__ ull pack2(float x, float y) {
    ull v;
    asm("mov.b64 %0, {%1, %2};" : "=l"(v)
        : "r"(__float_as_uint(x)), "r"(__float_as_uint(y)));
    return v;
}
__device__ __forceinline__ float2 unpack2(ull v) {
    unsigned a, b;
    asm("mov.b64 {%0, %1}, %2;" : "=r"(a), "=r"(b) : "l"(v));
    return make_float2(__uint_as_float(a), __uint_as_float(b));
}
#define FMA2(acc, a, b) \
    asm("fma.rn.f32x2 %0, %1, %2, %0;" : "+l"(acc) : "l"(a), "l"(b))

// ---------- fast activations (validated rel err ~4e-7 final) ----------
__device__ __forceinline__ float sigf(float x) {
    x = fminf(fmaxf(x, -30.f), 30.f);
    return __fdividef(1.f, 1.f + __expf(-x));
}
__device__ __forceinline__ float tanh_fast(float x) {
    x = fminf(fmaxf(x, -15.f), 15.f);
    float e = __expf(-2.f * x);
    return __fdividef(1.f - e, 1.f + e);
}

// ---------- cp.async helpers ----------
__device__ __forceinline__ unsigned smem_u32(const void* p) {
    return (unsigned)__cvta_generic_to_shared(p);
}
__device__ __forceinline__ void cp16(unsigned dst, const void* src) {
    asm volatile("cp.async.cg.shared.global [%0], [%1], 16;" :: "r"(dst), "l"(src));
}
#define CP_COMMIT() asm volatile("cp.async.commit_group;")
template<int N> __device__ __forceinline__ void cp_wait() {
    asm volatile("cp.async.wait_group %0;" :: "n"(N));
}

// =====================================================================
// Phase 1: input projections  pre[g][t][h][b] = sum_i x[t,b,i] * Wxg[h,i]
// One CTA per t; warp processes 4 gate-rows at a time (x loads amortized).
// =====================================================================
__global__ void __launch_bounds__(256, 1) k_input_proj(
    const float* __restrict__ x,
    const float* __restrict__ Wxi, const float* __restrict__ Wxf,
    const float* __restrict__ Wxo, const float* __restrict__ Wxc)
{
    extern __shared__ float xs[];          // [85][258]
    const int t = blockIdx.x;
    const float* xt = x + (size_t)t * BB * DIN;
    for (int idx = threadIdx.x; idx < BB * DIN; idx += 256) {
        int b = idx / DIN;
        int i = idx - b * DIN;
        xs[i * 258 + b] = xt[idx];
    }
    __syncthreads();

    const int warp = threadIdx.x >> 5;
    const int lane = threadIdx.x & 31;

    for (int r4 = warp * 4; r4 < 4 * HH; r4 += 32) {
        const int g = r4 >> 9;
        const int h = r4 & (HH - 1);
        const float* wrow;
        if      (g == 0) wrow = Wxi + h * DIN;
        else if (g == 1) wrow = Wxf + h * DIN;
        else if (g == 2) wrow = Wxo + h * DIN;
        else             wrow = Wxc + h * DIN;

        ull acc[4][4];
#pragma unroll
        for (int rr = 0; rr < 4; rr++)
#pragma unroll
            for (int q = 0; q < 4; q++) acc[rr][q] = 0;

#pragma unroll 5
        for (int i = 0; i < DIN; i++) {
            const ull* xr = (const ull*)(xs + i * 258);
            ull x0 = xr[lane], x1 = xr[lane + 32];
            ull x2 = xr[lane + 64], x3 = xr[lane + 96];
#pragma unroll
            for (int rr = 0; rr < 4; rr++) {
                float w = __ldg(wrow + rr * DIN + i);
                ull w2 = pack2(w, w);
                FMA2(acc[rr][0], w2, x0);
                FMA2(acc[rr][1], w2, x1);
                FMA2(acc[rr][2], w2, x2);
                FMA2(acc[rr][3], w2, x3);
            }
        }
#pragma unroll
        for (int rr = 0; rr < 4; rr++) {
            ull* pp = (ull*)(g_pre + (size_t)g * GSc +
                             ((size_t)t * HH + h + rr) * BB);
            pp[lane]      = acc[rr][0];
            pp[lane + 32] = acc[rr][1];
            pp[lane + 64] = acc[rr][2];
            pp[lane + 96] = acc[rr][3];
        }
    }
}

// =====================================================================
// Phase 2: persistent recurrence. 256 CTAs x 256 threads, 2 CTAs/SM.
// CTA tile: 8 h (32 gate rows) x 64 b.
//   hblk = blockIdx.x >> 2 -> h0 = hblk*8   (64 h-blocks)
//   grp  = blockIdx.x & 3  -> b0 = grp*64   (4 b-groups)
// Thread: hm = tid & 7 (one h, 4 gates), bq = tid >> 3 (2 b values).
// SMEM (112 KB total -> 2 CTAs/SM = 16 warps/SM):
//   sW[512 k][8 h] ulonglong2 {wI,wF},{wO,wC}   (64 KB, resident)
//   sH triple buffer 3 x [64 k][64 b]           (48 KB) cp.async ahead-1
// Barrier: round-6 generation barrier with nanosleep backoff.
// =====================================================================
__global__ void __launch_bounds__(256, 2) k_lstm_rec(
    const float* __restrict__ Whi, const float* __restrict__ Whf,
    const float* __restrict__ Who, const float* __restrict__ Whc,
    const float* __restrict__ bhi, const float* __restrict__ bhf,
    const float* __restrict__ bho, const float* __restrict__ bhc)
{
    extern __shared__ float smem_f[];
    ull*   sW = (ull*)smem_f;               // 8192 ull  = 64 KB
    float* sH = smem_f + 16384;             // 3 x 4096 f = 48 KB
    const unsigned sH_u32 = smem_u32(sH);

    const int tid  = threadIdx.x;
    const int hm   = tid & 7;
    const int bq   = tid >> 3;              // 0..31
    const int hblk = blockIdx.x >> 2;       // 0..63
    const int grp  = blockIdx.x & 3;        // 0..3
    const int h0   = hblk * 8;
    const int h    = h0 + hm;
    const int b0   = grp * 64;
    const int bb   = b0 + bq * 2;           // this thread's 2 b values

    // One-time W load: sW[(k*8 + hl)*2 + half]:
    //   half0 = {wI,wF}, half1 = {wO,wC} of row h0+hl, col k
    for (int idx = tid; idx < 512 * 8 * 2; idx += 256) {
        int half = idx & 1;
        int hl   = (idx >> 1) & 7;
        int k    = idx >> 4;
        int src  = (h0 + hl) * HH + k;
        sW[idx] = half ? pack2(Who[src], Whc[src])
                       : pack2(Whi[src], Whf[src]);
    }
    const float bi  = bhi[h], bf_ = bhf[h], bo = bho[h], bc = bhc[h];
    float C0 = 0.f, C1 = 0.f;
    __syncthreads();

    const ulonglong2* wbase = (const ulonglong2*)sW + hm;  // stride 8 per k

#pragma unroll 1
    for (int t = 0; t < TT; t++) {
        // Prefetch gate pre-activations (hidden under the GEMM)
        const float* pb = g_pre + ((size_t)t * HH + h) * BB + bb;
        float2 xi = *(const float2*)(pb);
        float2 xf = *(const float2*)(pb + GSc);
        float2 xo = *(const float2*)(pb + 2 * GSc);
        float2 xc = *(const float2*)(pb + 3 * GSc);

        ull aIF0 = 0, aOC0 = 0, aIF1 = 0, aOC1 = 0;

        if (t > 0) {
            const float* hsrc = g_hid + (size_t)(t - 1) * HH * BB + b0;

            // stage chunk 0 (k rows 0..63, 64 b cols = 16 KB) into buf 0
            {
#pragma unroll
                for (int j = 0; j < 4; j++) {
                    int i = tid + j * 256;          // 0..1023
                    int row = i >> 4, col = i & 15;
                    cp16(sH_u32 + (unsigned)i * 16, hsrc + row * BB + col * 4);
                }
                CP_COMMIT();
            }

#pragma unroll 1
            for (int c = 0; c < 8; c++) {
                if (c < 7) {   // stage chunk c+1 into buf (c+1)%3
                    const float* src = hsrc + (size_t)(c + 1) * 64 * BB;
                    unsigned dstb = sH_u32 + (unsigned)(((c + 1) % 3) * 16384);
#pragma unroll
                    for (int j = 0; j < 4; j++) {
                        int i = tid + j * 256;
                        int row = i >> 4, col = i & 15;
                        cp16(dstb + (unsigned)i * 16, src + row * BB + col * 4);
                    }
                    CP_COMMIT();
                    cp_wait<1>();
                } else {
                    cp_wait<0>();
                }
                __syncthreads();   // single sync per chunk (triple buffer,
                                   // stage target (c+1)%3 != c%3, (c-1)%3)

                const ulonglong2* wp = wbase + (size_t)c * 64 * 8;
                const float2* hp = (const float2*)(sH + (c % 3) * 4096) + bq;

#pragma unroll 8
                for (int kl = 0; kl < 64; kl++) {
                    ulonglong2 w = wp[kl * 8];      // {wI,wF},{wO,wC}
                    float2 hv = hp[kl * 32];        // 2 b values
                    ull h0d = pack2(hv.x, hv.x);
                    ull h1d = pack2(hv.y, hv.y);
                    FMA2(aIF0, w.x, h0d); FMA2(aOC0, w.y, h0d);
                    FMA2(aIF1, w.x, h1d); FMA2(aOC1, w.y, h1d);
                }
            }
        }

        // ---- epilogue: gates -> cell update -> hidden state (2 b) ----
        float hv0, hv1;
        {
            float2 vIF = unpack2(aIF0), vOC = unpack2(aOC0);
            float I = sigf(vIF.x + xi.x + bi), F = sigf(vIF.y + xf.x + bf_);
            float O = sigf(vOC.x + xo.x + bo), G = tanh_fast(vOC.y + xc.x + bc);
            C0 = F * C0 + I * G;  hv0 = O * tanh_fast(C0);
        }
        {
            float2 vIF = unpack2(aIF1), vOC = unpack2(aOC1);
            float I = sigf(vIF.x + xi.y + bi), F = sigf(vIF.y + xf.y + bf_);
            float O = sigf(vOC.x + xo.y + bo), G = tanh_fast(vOC.y + xc.y + bc);
            C1 = F * C1 + I * G;  hv1 = O * tanh_fast(C1);
        }

        *(float2*)(g_hid + ((size_t)t * HH + h) * BB + bb) =
            make_float2(hv0, hv1);

        // ---- grid barrier (round-6 generation barrier, 256 arrivals) ----
        if (t < TT - 1) {
            __threadfence();
            __syncthreads();
            if (tid == 0) {
                unsigned oldg = g_gen;
                if (atomicAdd(&g_cnt, 1u) == gridDim.x - 1) {
                    g_cnt = 0;
                    __threadfence();
                    g_gen = oldg + 1;
                } else {
                    while (g_gen == oldg) { __nanosleep(32); }
                }
                __threadfence();
            }
            __syncthreads();
        }
    }
}

// =====================================================================
// Phase 3: readout  out[t][b][o] = sum_h hid[t][h][b]*Wro[o][h] + bro[o]
// =====================================================================
__global__ void __launch_bounds__(256, 1) k_readout(
    const float* __restrict__ Wro, const float* __restrict__ bro,
    float* __restrict__ out)
{
    extern __shared__ float ws[];          // [33][512]
    for (int idx = threadIdx.x; idx < NOUT * HH; idx += 256)
        ws[idx] = Wro[idx];
    __syncthreads();

    const int warp = threadIdx.x >> 5;
    const int lane = threadIdx.x & 31;
    const int t = blockIdx.x;
    const int b = warp * 32 + lane;
    const float* hp = g_hid + (size_t)t * HH * BB + b;

    ull acc[NOUT];
#pragma unroll
    for (int o = 0; o < NOUT; o++) acc[o] = 0;

    for (int hh = 0; hh < HH; hh += 2) {
        float hv0 = hp[(size_t)hh * BB];
        float hv1 = hp[(size_t)(hh + 1) * BB];
        ull hv = pack2(hv0, hv1);
        const ull* wp = (const ull*)(ws + hh);
#pragma unroll
        for (int o = 0; o < NOUT; o++)
            FMA2(acc[o], hv, wp[o * 256]);
    }

    float* op = out + ((size_t)t * BB + b) * NOUT;
#pragma unroll
    for (int o = 0; o < NOUT; o++) {
        float2 v = unpack2(acc[o]);
        op[o] = v.x + v.y + bro[o];
    }
}

// =====================================================================
extern "C" void kernel_launch(void* const* d_in, const int* in_sizes, int n_in,
                              void* d_out, int out_size)
{
    const float* x   = (const float*)d_in[0];
    const float* Wxi = (const float*)d_in[1];
    const float* Wxf = (const float*)d_in[2];
    const float* Wxo = (const float*)d_in[3];
    const float* Wxc = (const float*)d_in[4];
    const float* Whi = (const float*)d_in[5];
    const float* bhi = (const float*)d_in[6];
    const float* Whf = (const float*)d_in[7];
    const float* bhf = (const float*)d_in[8];
    const float* Who = (const float*)d_in[9];
    const float* bho = (const float*)d_in[10];
    const float* Whc = (const float*)d_in[11];
    const float* bhc = (const float*)d_in[12];
    const float* Wro = (const float*)d_in[13];
    const float* bro = (const float*)d_in[14];
    float* out = (float*)d_out;

    const int smem_p1 = 85 * 258 * 4;               // 87,720 B
    const int smem_p2 = (16384 + 3 * 4096) * 4;     // 114,688 B (2 CTAs/SM)
    const int smem_p3 = NOUT * HH * 4;              // 67,584 B

    cudaFuncSetAttribute(k_input_proj, cudaFuncAttributeMaxDynamicSharedMemorySize, smem_p1);
    cudaFuncSetAttribute(k_lstm_rec,   cudaFuncAttributeMaxDynamicSharedMemorySize, smem_p2);
    cudaFuncSetAttribute(k_readout,    cudaFuncAttributeMaxDynamicSharedMemorySize, smem_p3);

    k_input_proj<<<TT, 256, smem_p1>>>(x, Wxi, Wxf, Wxo, Wxc);
    k_lstm_rec<<<256, 256, smem_p2>>>(Whi, Whf, Who, Whc, bhi, bhf, bho, bhc);
    k_readout<<<TT, 256, smem_p3>>>(Wro, bro, out);
}

// round 16
// speedup vs baseline: 2.0955x; 1.3485x over previous
#include <cuda_runtime.h>

typedef unsigned long long ull;

#define TT   512
#define BB   256
#define DIN  85
#define HH   512
#define NOUT 33

constexpr size_t GSc = (size_t)TT * HH * BB;   // elements per gate

// Scratch (allocation-free rule: __device__ globals)
__device__ float g_pre[4 * GSc];   // [gate][t][h][b]
__device__ float g_hid[GSc];       // [t][grp][h][b64]  (grp-blocked, contiguous slices)
__device__ unsigned g_cnt = 0;
__device__ volatile unsigned g_gen = 0;

// ---------- packed fp32x2 helpers ----------
__device__ __forceinline__ ull pack2(float x, float y) {
    ull v;
    asm("mov.b64 %0, {%1, %2};" : "=l"(v)
        : "r"(__float_as_uint(x)), "r"(__float_as_uint(y)));
    return v;
}
__device__ __forceinline__ float2 unpack2(ull v) {
    unsigned a, b;
    asm("mov.b64 {%0, %1}, %2;" : "=r"(a), "=r"(b) : "l"(v));
    return make_float2(__uint_as_float(a), __uint_as_float(b));
}
#define FMA2(acc, a, b) \
    asm("fma.rn.f32x2 %0, %1, %2, %0;" : "+l"(acc) : "l"(a), "l"(b))

// ---------- fast activations (validated rel err ~4e-7 final) ----------
__device__ __forceinline__ float sigf(float x) {
    x = fminf(fmaxf(x, -30.f), 30.f);
    return __fdividef(1.f, 1.f + __expf(-x));
}
__device__ __forceinline__ float tanh_fast(float x) {
    x = fminf(fmaxf(x, -15.f), 15.f);
    float e = __expf(-2.f * x);
    return __fdividef(1.f - e, 1.f + e);
}

// ---------- smem/TMA/mbarrier helpers ----------
__device__ __forceinline__ unsigned smem_u32(const void* p) {
    return (unsigned)__cvta_generic_to_shared(p);
}
__device__ __forceinline__ void bulk_ld(unsigned dst, const void* src,
                                        unsigned bytes, unsigned mbar) {
    asm volatile(
        "cp.async.bulk.shared::cluster.global.mbarrier::complete_tx::bytes "
        "[%0], [%1], %2, [%3];"
        :: "r"(dst), "l"(src), "r"(bytes), "r"(mbar) : "memory");
}
#define MBAR_INIT(a, c) \
    asm volatile("mbarrier.init.shared.b64 [%0], %1;" :: "r"(a), "r"(c) : "memory")
#define MBAR_EXPECT_TX(a, b) \
    asm volatile("mbarrier.arrive.expect_tx.shared.b64 _, [%0], %1;" \
                 :: "r"(a), "r"((unsigned)(b)) : "memory")
__device__ __forceinline__ void mbar_wait(unsigned addr, unsigned parity) {
    asm volatile(
        "{\n\t"
        ".reg .pred P1;\n\t"
        "WAIT_LOOP_%=:\n\t"
        "mbarrier.try_wait.parity.acquire.cta.shared::cta.b64 P1, [%0], %1, 0x989680;\n\t"
        "@P1 bra.uni WAIT_DONE_%=;\n\t"
        "bra.uni WAIT_LOOP_%=;\n\t"
        "WAIT_DONE_%=:\n\t"
        "}"
        :: "r"(addr), "r"(parity) : "memory");
}

// =====================================================================
// Phase 1: input projections  pre[g][t][h][b] = sum_i x[t,b,i] * Wxg[h,i]
// =====================================================================
__global__ void __launch_bounds__(256, 1) k_input_proj(
    const float* __restrict__ x,
    const float* __restrict__ Wxi, const float* __restrict__ Wxf,
    const float* __restrict__ Wxo, const float* __restrict__ Wxc)
{
    extern __shared__ float xs[];          // [85][258]
    const int t = blockIdx.x;
    const float* xt = x + (size_t)t * BB * DIN;
    for (int idx = threadIdx.x; idx < BB * DIN; idx += 256) {
        int b = idx / DIN;
        int i = idx - b * DIN;
        xs[i * 258 + b] = xt[idx];
    }
    __syncthreads();

    const int warp = threadIdx.x >> 5;
    const int lane = threadIdx.x & 31;

    for (int r4 = warp * 4; r4 < 4 * HH; r4 += 32) {
        const int g = r4 >> 9;
        const int h = r4 & (HH - 1);
        const float* wrow;
        if      (g == 0) wrow = Wxi + h * DIN;
        else if (g == 1) wrow = Wxf + h * DIN;
        else if (g == 2) wrow = Wxo + h * DIN;
        else             wrow = Wxc + h * DIN;

        ull acc[4][4];
#pragma unroll
        for (int rr = 0; rr < 4; rr++)
#pragma unroll
            for (int q = 0; q < 4; q++) acc[rr][q] = 0;

#pragma unroll 5
        for (int i = 0; i < DIN; i++) {
            const ull* xr = (const ull*)(xs + i * 258);
            ull x0 = xr[lane], x1 = xr[lane + 32];
            ull x2 = xr[lane + 64], x3 = xr[lane + 96];
#pragma unroll
            for (int rr = 0; rr < 4; rr++) {
                float w = __ldg(wrow + rr * DIN + i);
                ull w2 = pack2(w, w);
                FMA2(acc[rr][0], w2, x0);
                FMA2(acc[rr][1], w2, x1);
                FMA2(acc[rr][2], w2, x2);
                FMA2(acc[rr][3], w2, x3);
            }
        }
#pragma unroll
        for (int rr = 0; rr < 4; rr++) {
            ull* pp = (ull*)(g_pre + (size_t)g * GSc +
                             ((size_t)t * HH + h + rr) * BB);
            pp[lane]      = acc[rr][0];
            pp[lane + 32] = acc[rr][1];
            pp[lane + 64] = acc[rr][2];
            pp[lane + 96] = acc[rr][3];
        }
    }
}

// =====================================================================
// Phase 2: persistent recurrence (R6 config + TMA bulk staging).
// 128 CTAs x 256 threads. CTA tile: 16 h (64 gate rows) x 64 b.
//   hblk = blockIdx.x & 31  -> h0 = hblk*16
//   grp  = blockIdx.x >> 5  -> b-group (64 b each)
// Thread: h_me = tid & 15 (one h, 4 gates), bq = tid >> 4 (4 b values).
// SMEM: sWs[512 k][64 rows] fp32 (128 KB) + sH double buffer 2x32 KB,
//       staged via ONE cp.async.bulk per 32 KB chunk (MLP_p1 ~ 1).
// g_hid layout [t][grp][h][64] makes each chunk contiguous in GMEM.
// =====================================================================
__global__ void __launch_bounds__(256, 1) k_lstm_rec(
    const float* __restrict__ Whi, const float* __restrict__ Whf,
    const float* __restrict__ Who, const float* __restrict__ Whc,
    const float* __restrict__ bhi, const float* __restrict__ bhf,
    const float* __restrict__ bho, const float* __restrict__ bhc)
{
    extern __shared__ float smem_f[];
    float* sWs = smem_f;                    // 32768 floats (128 KB)
    float* sH  = smem_f + 32768;            // 2 x 8192 floats (64 KB)
    const unsigned sH_u32   = smem_u32(sH);
    const unsigned mbar0    = smem_u32(smem_f + 49152);   // 2 mbarriers
    const unsigned mbar1    = mbar0 + 8;

    const int tid  = threadIdx.x;
    const int h_me = tid & 15;
    const int bq   = tid >> 4;              // 0..15
    const int hblk = blockIdx.x & 31;
    const int grp  = blockIdx.x >> 5;       // 0..3
    const int h0   = hblk * 16;
    const int h    = h0 + h_me;
    const int bglob = grp * 64 + bq * 4;    // global batch base (g_pre)

    // One-time W load: sWs[k*64 + hm*4 + g] = W_g[h0+hm][k]
    for (int idx = tid; idx < 512 * 64; idx += 256) {
        int r  = idx & 63;
        int k  = idx >> 6;
        int hm = r >> 2;
        int g  = r & 3;
        int src = (h0 + hm) * HH + k;
        float w;
        if      (g == 0) w = Whi[src];
        else if (g == 1) w = Whf[src];
        else if (g == 2) w = Who[src];
        else             w = Whc[src];
        sWs[idx] = w;
    }
    if (tid == 0) {
        MBAR_INIT(mbar0, 1);
        MBAR_INIT(mbar1, 1);
    }
    const float bi  = bhi[h], bf_ = bhf[h], bo = bho[h], bc = bhc[h];
    float C0 = 0.f, C1 = 0.f, C2 = 0.f, C3 = 0.f;
    __syncthreads();
    if (tid == 0)
        asm volatile("fence.proxy.async.shared::cta;" ::: "memory");
    __syncthreads();

#pragma unroll 1
    for (int t = 0; t < TT; t++) {
        // Prefetch gate pre-activations (independent of Hs -> hidden by GEMM)
        const float* pb = g_pre + ((size_t)t * HH + h) * BB + bglob;
        float4 xi = *(const float4*)(pb);
        float4 xf = *(const float4*)(pb + GSc);
        float4 xo = *(const float4*)(pb + 2 * GSc);
        float4 xc = *(const float4*)(pb + 3 * GSc);

        ull aIF0 = 0, aIF1 = 0, aIF2 = 0, aIF3 = 0;
        ull aOC0 = 0, aOC1 = 0, aOC2 = 0, aOC3 = 0;

        if (t > 0) {
            // this CTA's contiguous 128 KB Hs slice (grp block)
            const float* hsrc =
                g_hid + (((size_t)(t - 1) * 4 + grp) << 15);   // *32768 floats

            if (tid == 0) {   // stage chunk 0 (k rows 0..127 = 32 KB)
                MBAR_EXPECT_TX(mbar0, 32768);
                bulk_ld(sH_u32, hsrc, 32768, mbar0);
            }

#pragma unroll 1
            for (int c = 0; c < 4; c++) {
                if (c < 3 && tid == 0) {   // stage chunk c+1 (other buffer)
                    unsigned mb = ((c + 1) & 1) ? mbar1 : mbar0;
                    MBAR_EXPECT_TX(mb, 32768);
                    bulk_ld(sH_u32 + (unsigned)(((c + 1) & 1) * 32768),
                            hsrc + (size_t)(c + 1) * 8192, 32768, mb);
                }
                // wait for chunk c (each mbar flips twice per step:
                // parity for chunk c is (c>>1)&1, step-invariant)
                mbar_wait((c & 1) ? mbar1 : mbar0, (unsigned)((c >> 1) & 1));

                const ulonglong2* wp2 =
                    (const ulonglong2*)sWs + (size_t)c * 2048 + h_me;
                const float4* hb4 =
                    (const float4*)(sH + (c & 1) * 8192) + bq;

#pragma unroll 4
                for (int kk = 0; kk < 128; kk++) {
                    ulonglong2 w2 = wp2[kk * 16];      // {wI,wF},{wO,wC}
                    float4 hv = hb4[kk * 16];          // 4 b values
                    ull h0d = pack2(hv.x, hv.x);
                    ull h1d = pack2(hv.y, hv.y);
                    ull h2d = pack2(hv.z, hv.z);
                    ull h3d = pack2(hv.w, hv.w);
                    FMA2(aIF0, w2.x, h0d); FMA2(aOC0, w2.y, h0d);
                    FMA2(aIF1, w2.x, h1d); FMA2(aOC1, w2.y, h1d);
                    FMA2(aIF2, w2.x, h2d); FMA2(aOC2, w2.y, h2d);
                    FMA2(aIF3, w2.x, h3d); FMA2(aOC3, w2.y, h3d);
                }
                __syncthreads();   // bounds thread lag: safe buffer reuse
            }
        }

        // Epilogue: gates -> cell update -> hidden state
        float hv0, hv1, hv2, hv3;
        {
            float2 vIF = unpack2(aIF0), vOC = unpack2(aOC0);
            float I = sigf(vIF.x + xi.x + bi);
            float F = sigf(vIF.y + xf.x + bf_);
            float O = sigf(vOC.x + xo.x + bo);
            float G = tanh_fast(vOC.y + xc.x + bc);
            C0 = F * C0 + I * G;  hv0 = O * tanh_fast(C0);
        }
        {
            float2 vIF = unpack2(aIF1), vOC = unpack2(aOC1);
            float I = sigf(vIF.x + xi.y + bi);
            float F = sigf(vIF.y + xf.y + bf_);
            float O = sigf(vOC.x + xo.y + bo);
            float G = tanh_fast(vOC.y + xc.y + bc);
            C1 = F * C1 + I * G;  hv1 = O * tanh_fast(C1);
        }
        {
            float2 vIF = unpack2(aIF2), vOC = unpack2(aOC2);
            float I = sigf(vIF.x + xi.z + bi);
            float F = sigf(vIF.y + xf.z + bf_);
            float O = sigf(vOC.x + xo.z + bo);
            float G = tanh_fast(vOC.y + xc.z + bc);
            C2 = F * C2 + I * G;  hv2 = O * tanh_fast(C2);
        }
        {
            float2 vIF = unpack2(aIF3), vOC = unpack2(aOC3);
            float I = sigf(vIF.x + xi.w + bi);
            float F = sigf(vIF.y + xf.w + bf_);
            float O = sigf(vOC.x + xo.w + bo);
            float G = tanh_fast(vOC.y + xc.w + bc);
            C3 = F * C3 + I * G;  hv3 = O * tanh_fast(C3);
        }

        // write Hs in grp-blocked layout: [t][grp][h][b64]
        *(float4*)(g_hid + (((size_t)t * 4 + grp) * HH + h) * 64 + bq * 4) =
            make_float4(hv0, hv1, hv2, hv3);

        // ---- grid barrier (generation barrier, 128 arrivals) ----
        if (t < TT - 1) {
            __threadfence();
            __syncthreads();
            if (tid == 0) {
                unsigned oldg = g_gen;
                if (atomicAdd(&g_cnt, 1u) == gridDim.x - 1) {
                    g_cnt = 0;
                    __threadfence();
                    g_gen = oldg + 1;
                } else {
                    while (g_gen == oldg) { __nanosleep(32); }
                }
                __threadfence();
            }
            __syncthreads();
        }
    }
}

// =====================================================================
// Phase 3: readout  out[t][b][o] = sum_h hid[t][grp][h][bl]*Wro[o][h] + bro[o]
// =====================================================================
__global__ void __launch_bounds__(256, 1) k_readout(
    const float* __restrict__ Wro, const float* __restrict__ bro,
    float* __restrict__ out)
{
    extern __shared__ float ws[];          // [33][512]
    for (int idx = threadIdx.x; idx < NOUT * HH; idx += 256)
        ws[idx] = Wro[idx];
    __syncthreads();

    const int warp = threadIdx.x >> 5;
    const int lane = threadIdx.x & 31;
    const int t = blockIdx.x;
    const int b = warp * 32 + lane;
    const float* hp = g_hid + (size_t)t * HH * BB +
                      (size_t)(b >> 6) * (HH * 64) + (b & 63);

    ull acc[NOUT];
#pragma unroll
    for (int o = 0; o < NOUT; o++) acc[o] = 0;

    for (int hh = 0; hh < HH; hh += 2) {
        float hv0 = hp[(size_t)hh * 64];
        float hv1 = hp[(size_t)(hh + 1) * 64];
        ull hv = pack2(hv0, hv1);
        const ull* wp = (const ull*)(ws + hh);
#pragma unroll
        for (int o = 0; o < NOUT; o++)
            FMA2(acc[o], hv, wp[o * 256]);
    }

    float* op = out + ((size_t)t * BB + b) * NOUT;
#pragma unroll
    for (int o = 0; o < NOUT; o++) {
        float2 v = unpack2(acc[o]);
        op[o] = v.x + v.y + bro[o];
    }
}

// =====================================================================
extern "C" void kernel_launch(void* const* d_in, const int* in_sizes, int n_in,
                              void* d_out, int out_size)
{
    const float* x   = (const float*)d_in[0];
    const float* Wxi = (const float*)d_in[1];
    const float* Wxf = (const float*)d_in[2];
    const float* Wxo = (const float*)d_in[3];
    const float* Wxc = (const float*)d_in[4];
    const float* Whi = (const float*)d_in[5];
    const float* bhi = (const float*)d_in[6];
    const float* Whf = (const float*)d_in[7];
    const float* bhf = (const float*)d_in[8];
    const float* Who = (const float*)d_in[9];
    const float* bho = (const float*)d_in[10];
    const float* Whc = (const float*)d_in[11];
    const float* bhc = (const float*)d_in[12];
    const float* Wro = (const float*)d_in[13];
    const float* bro = (const float*)d_in[14];
    float* out = (float*)d_out;

    const int smem_p1 = 85 * 258 * 4;                    // 87,720 B
    const int smem_p2 = (32768 + 2 * 8192) * 4 + 64;     // 196,672 B
    const int smem_p3 = NOUT * HH * 4;                   // 67,584 B

    cudaFuncSetAttribute(k_input_proj, cudaFuncAttributeMaxDynamicSharedMemorySize, smem_p1);
    cudaFuncSetAttribute(k_lstm_rec,   cudaFuncAttributeMaxDynamicSharedMemorySize, smem_p2);
    cudaFuncSetAttribute(k_readout,    cudaFuncAttributeMaxDynamicSharedMemorySize, smem_p3);

    k_input_proj<<<TT, 256, smem_p1>>>(x, Wxi, Wxf, Wxo, Wxc);
    k_lstm_rec<<<128, 256, smem_p2>>>(Whi, Whf, Who, Whc, bhi, bhf, bho, bhc);
    k_readout<<<TT, 256, smem_p3>>>(Wro, bro, out);
}